// round 11
// baseline (speedup 1.0000x reference)
#include <cuda_runtime.h>

#define NMAX 50176
#define EMAX 810000

// ---------------- scratch (static __device__ — no allocation allowed) ----------------
__device__ int   g_is64;                      // 1 if edge_index is int64, 0 if int32
__device__ int   g_deg[NMAX];
__device__ int   g_rowstart[NMAX + 1];
__device__ int   g_cursor[NMAX];
__device__ int   g_csr[EMAX];
__device__ float g_invdeg[NMAX];
__device__ float g_h1[(size_t)NMAX * 128];   // gather1 output (mean of x)
__device__ float g_h2[(size_t)NMAX * 128];   // relu(h1 @ W1 + b1) * mask
__device__ float g_h3[(size_t)NMAX * 128];   // gather2 output (mean of h2)

// ---------------- edge-index dtype detection ----------------
// int32 data read as int64 gives value = lo + hi*2^32 with hi = next node id
// (~never 0 for 256 consecutive entries). True int64 node ids are all < n.
__global__ void detect_kernel(const void* __restrict__ ei, int n) {
    __shared__ int bad;
    if (threadIdx.x == 0) bad = 0;
    __syncthreads();
    long long v = ((const long long*)ei)[threadIdx.x];
    if (v < 0 || v >= (long long)n) atomicOr(&bad, 1);
    __syncthreads();
    if (threadIdx.x == 0) g_is64 = bad ? 0 : 1;
}

__device__ __forceinline__ int load_idx(const void* ei, long long pos) {
    if (g_is64) return (int)((const long long*)ei)[pos];
    return ((const int*)ei)[pos];
}

// ---------------- CSR build ----------------

__global__ void zero_deg_kernel(int n) {
    int i = blockIdx.x * blockDim.x + threadIdx.x;
    if (i < n) g_deg[i] = 0;
}

__global__ void count_kernel(const void* __restrict__ ei, int E, int n) {
    int e = blockIdx.x * blockDim.x + threadIdx.x;
    if (e < E) {
        int dst = load_idx(ei, (long long)E + e);
        if ((unsigned)dst < (unsigned)n) atomicAdd(&g_deg[dst], 1);
    }
}

// single-block exclusive scan over deg -> row_start, cursor; also inv_deg
__global__ __launch_bounds__(1024) void scan_kernel(int n) {
    __shared__ int wsum[32];
    __shared__ int carry;
    int tid = threadIdx.x, lane = tid & 31, wid = tid >> 5;
    if (tid == 0) carry = 0;
    __syncthreads();
    for (int base = 0; base < n; base += 1024) {
        int i = base + tid;
        int v = (i < n) ? g_deg[i] : 0;
        int x = v;
        #pragma unroll
        for (int o = 1; o < 32; o <<= 1) {
            int y = __shfl_up_sync(0xffffffffu, x, o);
            if (lane >= o) x += y;
        }
        if (lane == 31) wsum[wid] = x;
        __syncthreads();
        if (wid == 0) {
            int s = wsum[lane];
            #pragma unroll
            for (int o = 1; o < 32; o <<= 1) {
                int y = __shfl_up_sync(0xffffffffu, s, o);
                if (lane >= o) s += y;
            }
            wsum[lane] = s;
        }
        __syncthreads();
        int excl = x - v + (wid > 0 ? wsum[wid - 1] : 0) + carry;
        if (i < n) {
            g_rowstart[i] = excl;
            g_cursor[i]   = excl;
            g_invdeg[i]   = 1.0f / (float)max(v, 1);
        }
        __syncthreads();
        if (tid == 1023) carry = excl + v;
        __syncthreads();
    }
    if (tid == 0) g_rowstart[n] = carry;
}

__global__ void fill_kernel(const void* __restrict__ ei, int E, int n) {
    int e = blockIdx.x * blockDim.x + threadIdx.x;
    if (e < E) {
        int src = load_idx(ei, e);
        int dst = load_idx(ei, (long long)E + e);
        if ((unsigned)dst < (unsigned)n && (unsigned)src < (unsigned)n) {
            int slot = atomicAdd(&g_cursor[dst], 1);
            if (slot < EMAX) g_csr[slot] = src;
        }
    }
}

// ---------------- gather-mean: one warp per node, conflict-free, no atomics ----------------

__device__ __forceinline__ void gather_impl(const float* __restrict__ feat,
                                            float* __restrict__ outp, int n) {
    int w    = (blockIdx.x * blockDim.x + threadIdx.x) >> 5;
    int lane = threadIdx.x & 31;
    if (w >= n) return;
    int s = g_rowstart[w];
    int e = g_rowstart[w + 1];
    const float4* f4 = (const float4*)feat;
    float4 a0 = make_float4(0.f, 0.f, 0.f, 0.f);
    float4 a1 = make_float4(0.f, 0.f, 0.f, 0.f);
    int i = s;
    for (; i + 32 <= e; i += 32) {
        int sv = g_csr[i + lane];
        #pragma unroll
        for (int j = 0; j < 32; j += 2) {
            int s0 = __shfl_sync(0xffffffffu, sv, j);
            int s1 = __shfl_sync(0xffffffffu, sv, j + 1);
            float4 v0 = f4[(size_t)s0 * 32 + lane];
            float4 v1 = f4[(size_t)s1 * 32 + lane];
            a0.x += v0.x; a0.y += v0.y; a0.z += v0.z; a0.w += v0.w;
            a1.x += v1.x; a1.y += v1.y; a1.z += v1.z; a1.w += v1.w;
        }
    }
    int rem = e - i;
    if (rem > 0) {
        int sv = (lane < rem) ? g_csr[i + lane] : 0;
        int j = 0;
        for (; j + 1 < rem; j += 2) {
            int s0 = __shfl_sync(0xffffffffu, sv, j);
            int s1 = __shfl_sync(0xffffffffu, sv, j + 1);
            float4 v0 = f4[(size_t)s0 * 32 + lane];
            float4 v1 = f4[(size_t)s1 * 32 + lane];
            a0.x += v0.x; a0.y += v0.y; a0.z += v0.z; a0.w += v0.w;
            a1.x += v1.x; a1.y += v1.y; a1.z += v1.z; a1.w += v1.w;
        }
        if (j < rem) {
            int s0 = __shfl_sync(0xffffffffu, sv, j);
            float4 v0 = f4[(size_t)s0 * 32 + lane];
            a0.x += v0.x; a0.y += v0.y; a0.z += v0.z; a0.w += v0.w;
        }
    }
    float id = g_invdeg[w];
    float4 r;
    r.x = (a0.x + a1.x) * id;
    r.y = (a0.y + a1.y) * id;
    r.z = (a0.z + a1.z) * id;
    r.w = (a0.w + a1.w) * id;
    ((float4*)outp)[(size_t)w * 32 + lane] = r;
}

__global__ __launch_bounds__(256) void gather1_kernel(const float* __restrict__ x, int n) {
    gather_impl(x, g_h1, n);
}
__global__ __launch_bounds__(256) void gather2_kernel(int n) {
    gather_impl(g_h2, g_h3, n);
}

// ---------------- GEMM1: h2 = relu(h1 @ W1 + b1) * mask ----------------
// BM=64, BN=128, BK=32. 256 threads, 4x8 register tile each. 24.7 KB static smem.

__global__ __launch_bounds__(256) void gemm1_kernel(const float* __restrict__ W1,
                                                    const float* __restrict__ b1,
                                                    const float* __restrict__ mask,
                                                    int n) {
    __shared__ __align__(16) float As[64 * 32];
    __shared__ __align__(16) float Ws[32 * 128];
    __shared__ __align__(16) float bs[128];
    int tid = threadIdx.x;

    if (tid < 32)
        ((float4*)bs)[tid] = ((const float4*)b1)[tid];

    int row0 = blockIdx.x * 64;
    int ty = tid >> 4, tx = tid & 15;
    float acc[4][8];
    #pragma unroll
    for (int i = 0; i < 4; i++)
        #pragma unroll
        for (int j = 0; j < 8; j++) acc[i][j] = 0.f;

    for (int kc = 0; kc < 4; kc++) {        // K chunks of 32
        #pragma unroll
        for (int t = 0; t < 2; t++) {
            int idx = tid + t * 256;        // 0..511
            int r = idx >> 3, c4 = idx & 7;
            int gr = row0 + r;
            float4 v = (gr < n) ? ((const float4*)g_h1)[(size_t)gr * 32 + kc * 8 + c4]
                                : make_float4(0.f, 0.f, 0.f, 0.f);
            *(float4*)&As[r * 32 + c4 * 4] = v;
        }
        #pragma unroll
        for (int t = 0; t < 4; t++) {
            int idx = tid + t * 256;        // 0..1023
            int r = idx >> 5, c4 = idx & 31;
            ((float4*)Ws)[idx] = ((const float4*)W1)[(size_t)(kc * 32 + r) * 32 + c4];
        }
        __syncthreads();

        #pragma unroll 8
        for (int kk = 0; kk < 32; kk++) {
            float4 w0 = *(float4*)&Ws[kk * 128 + tx * 4];
            float4 w1 = *(float4*)&Ws[kk * 128 + 64 + tx * 4];
            #pragma unroll
            for (int i = 0; i < 4; i++) {
                float a = As[(ty * 4 + i) * 32 + kk];
                acc[i][0] = fmaf(a, w0.x, acc[i][0]);
                acc[i][1] = fmaf(a, w0.y, acc[i][1]);
                acc[i][2] = fmaf(a, w0.z, acc[i][2]);
                acc[i][3] = fmaf(a, w0.w, acc[i][3]);
                acc[i][4] = fmaf(a, w1.x, acc[i][4]);
                acc[i][5] = fmaf(a, w1.y, acc[i][5]);
                acc[i][6] = fmaf(a, w1.z, acc[i][6]);
                acc[i][7] = fmaf(a, w1.w, acc[i][7]);
            }
        }
        __syncthreads();
    }

    float4 bv0 = *(float4*)&bs[tx * 4];
    float4 bv1 = *(float4*)&bs[64 + tx * 4];
    #pragma unroll
    for (int i = 0; i < 4; i++) {
        int gr = row0 + ty * 4 + i;
        if (gr < n) {
            float4 m0 = ((const float4*)mask)[(size_t)gr * 32 + tx];
            float4 m1 = ((const float4*)mask)[(size_t)gr * 32 + 16 + tx];
            float4 o0, o1;
            o0.x = fmaxf(acc[i][0] + bv0.x, 0.f) * m0.x;
            o0.y = fmaxf(acc[i][1] + bv0.y, 0.f) * m0.y;
            o0.z = fmaxf(acc[i][2] + bv0.z, 0.f) * m0.z;
            o0.w = fmaxf(acc[i][3] + bv0.w, 0.f) * m0.w;
            o1.x = fmaxf(acc[i][4] + bv1.x, 0.f) * m1.x;
            o1.y = fmaxf(acc[i][5] + bv1.y, 0.f) * m1.y;
            o1.z = fmaxf(acc[i][6] + bv1.z, 0.f) * m1.z;
            o1.w = fmaxf(acc[i][7] + bv1.w, 0.f) * m1.w;
            ((float4*)g_h2)[(size_t)gr * 32 + tx]      = o0;
            ((float4*)g_h2)[(size_t)gr * 32 + 16 + tx] = o1;
        }
    }
}

// ---------------- GEMM2: out = h3 @ W2 + b2  (C=16) ----------------

__global__ __launch_bounds__(128) void gemm2_kernel(const float* __restrict__ W2,
                                                    const float* __restrict__ b2,
                                                    float* __restrict__ out, int n) {
    __shared__ __align__(16) float As[32 * 132];
    __shared__ __align__(16) float W2s[128 * 16];
    __shared__ __align__(16) float b2s[16];
    int tid = threadIdx.x;

    for (int i = tid; i < 512; i += 128)
        ((float4*)W2s)[i] = ((const float4*)W2)[i];
    if (tid < 4)
        ((float4*)b2s)[tid] = ((const float4*)b2)[tid];

    int row0 = blockIdx.x * 32;
    for (int i = tid; i < 1024; i += 128) {
        int r = i >> 5, c4 = i & 31;
        int gr = row0 + r;
        float4 v = (gr < n) ? ((const float4*)g_h3)[(size_t)gr * 32 + c4]
                            : make_float4(0.f, 0.f, 0.f, 0.f);
        *(float4*)&As[r * 132 + c4 * 4] = v;
    }
    __syncthreads();

    int row = tid >> 2, cg = tid & 3;
    float4 acc = make_float4(0.f, 0.f, 0.f, 0.f);
    #pragma unroll 8
    for (int k = 0; k < 128; k++) {
        float a = As[row * 132 + k];
        float4 w = *(float4*)&W2s[k * 16 + cg * 4];
        acc.x = fmaf(a, w.x, acc.x);
        acc.y = fmaf(a, w.y, acc.y);
        acc.z = fmaf(a, w.z, acc.z);
        acc.w = fmaf(a, w.w, acc.w);
    }
    int gr = row0 + row;
    if (gr < n) {
        float4 b = *(float4*)&b2s[cg * 4];
        float4 o;
        o.x = acc.x + b.x; o.y = acc.y + b.y; o.z = acc.z + b.z; o.w = acc.w + b.w;
        ((float4*)out)[(size_t)gr * 4 + cg] = o;
    }
}

// ---------------- launch ----------------

extern "C" void kernel_launch(void* const* d_in, const int* in_sizes, int n_in,
                              void* d_out, int out_size) {
    const float* x    = (const float*)d_in[0];
    const void*  ei   = d_in[1];                 // int32 or int64, detected on device
    const float* W1   = (const float*)d_in[2];
    const float* b1   = (const float*)d_in[3];
    const float* W2   = (const float*)d_in[4];
    const float* b2   = (const float*)d_in[5];
    const float* mask = (const float*)d_in[6];
    float*       out  = (float*)d_out;

    int n = in_sizes[0] / 128;   // N nodes
    int E = in_sizes[1] / 2;     // edges (element count is 2E for either dtype)

    // dtype detection + CSR build
    detect_kernel<<<1, 256>>>(ei, n);
    zero_deg_kernel<<<(n + 255) / 256, 256>>>(n);
    count_kernel<<<(E + 255) / 256, 256>>>(ei, E, n);
    scan_kernel<<<1, 1024>>>(n);
    fill_kernel<<<(E + 255) / 256, 256>>>(ei, E, n);

    // layer 1
    gather1_kernel<<<(n * 32 + 255) / 256, 256>>>(x, n);
    gemm1_kernel<<<(n + 63) / 64, 256>>>(W1, b1, mask, n);

    // layer 2
    gather2_kernel<<<(n * 32 + 255) / 256, 256>>>(n);
    gemm2_kernel<<<(n + 31) / 32, 128>>>(W2, b2, out, n);
}

// round 16
// speedup vs baseline: 1.2217x; 1.2217x over previous
#include <cuda_runtime.h>

#define NMAX 50176
#define EMAX 810000
#define SCAN_B 1024
#define NBMAX 64   // ceil(NMAX/1024) = 49 <= 64

// ---------------- scratch (static __device__ — no allocation allowed) ----------------
__device__ int   g_is64;                      // 1 if edge_index is int64, 0 if int32
__device__ int   g_deg[NMAX];
__device__ int   g_rowstart[NMAX + 1];
__device__ int   g_cursor[NMAX];
__device__ int   g_bsum[NBMAX];
__device__ int   g_csr[EMAX];
__device__ float g_invdeg[NMAX];
__device__ float g_h1[(size_t)NMAX * 128];   // gather1 output (mean of x)
__device__ float g_h2[(size_t)NMAX * 128];   // relu(h1 @ W1 + b1) * mask
__device__ float g_h3[(size_t)NMAX * 128];   // gather2 output (mean of h2)

// ---------------- edge-index dtype detection ----------------
// int32 data read as int64 gives value = lo + hi*2^32 with hi = next node id
// (~never 0 for 256 consecutive entries). True int64 node ids are all < n.
__global__ void detect_kernel(const void* __restrict__ ei, int n) {
    __shared__ int bad;
    if (threadIdx.x == 0) bad = 0;
    __syncthreads();
    long long v = ((const long long*)ei)[threadIdx.x];
    if (v < 0 || v >= (long long)n) atomicOr(&bad, 1);
    __syncthreads();
    if (threadIdx.x == 0) g_is64 = bad ? 0 : 1;
}

__device__ __forceinline__ int load_idx(const void* ei, long long pos) {
    if (g_is64) return (int)((const long long*)ei)[pos];
    return ((const int*)ei)[pos];
}

// ---------------- CSR build ----------------

__global__ void zero_deg_kernel(int n) {
    int i = blockIdx.x * blockDim.x + threadIdx.x;
    if (i < n) g_deg[i] = 0;
}

__global__ void count_kernel(const void* __restrict__ ei, int E, int n) {
    int e = blockIdx.x * blockDim.x + threadIdx.x;
    if (e < E) {
        int dst = load_idx(ei, (long long)E + e);
        if ((unsigned)dst < (unsigned)n) atomicAdd(&g_deg[dst], 1);
    }
}

// ---------- 3-phase device-wide exclusive scan over g_deg ----------

// phase 1: block-local exclusive scan; block totals to g_bsum
__global__ __launch_bounds__(SCAN_B) void scan_phase1(int n) {
    __shared__ int wsum[32];
    int i = blockIdx.x * SCAN_B + threadIdx.x;
    int lane = threadIdx.x & 31, wid = threadIdx.x >> 5;
    int v = (i < n) ? g_deg[i] : 0;
    int x = v;
    #pragma unroll
    for (int o = 1; o < 32; o <<= 1) {
        int y = __shfl_up_sync(0xffffffffu, x, o);
        if (lane >= o) x += y;
    }
    if (lane == 31) wsum[wid] = x;
    __syncthreads();
    if (wid == 0) {
        int s = wsum[lane];
        #pragma unroll
        for (int o = 1; o < 32; o <<= 1) {
            int y = __shfl_up_sync(0xffffffffu, s, o);
            if (lane >= o) s += y;
        }
        wsum[lane] = s;
    }
    __syncthreads();
    int excl = x - v + (wid > 0 ? wsum[wid - 1] : 0);
    if (i < n) g_rowstart[i] = excl;
    if (threadIdx.x == SCAN_B - 1) g_bsum[blockIdx.x] = excl + v;
}

// phase 2: one tiny block scans the <=64 block sums; writes total to rowstart[n]
__global__ __launch_bounds__(NBMAX) void scan_phase2(int nb, int n) {
    __shared__ int s[NBMAX];
    int tid = threadIdx.x;
    int v = (tid < nb) ? g_bsum[tid] : 0;
    s[tid] = v;
    __syncthreads();
    #pragma unroll
    for (int o = 1; o < NBMAX; o <<= 1) {
        int t = (tid >= o) ? s[tid - o] : 0;
        __syncthreads();
        s[tid] += t;
        __syncthreads();
    }
    if (tid < nb) g_bsum[tid] = s[tid] - v;       // exclusive
    if (tid == nb - 1) g_rowstart[n] = s[tid];    // total
}

// phase 3: add block offsets, emit rowstart/cursor/invdeg
__global__ __launch_bounds__(SCAN_B) void scan_phase3(int n) {
    int i = blockIdx.x * SCAN_B + threadIdx.x;
    if (i < n) {
        int rs = g_rowstart[i] + g_bsum[blockIdx.x];
        g_rowstart[i] = rs;
        g_cursor[i]   = rs;
        g_invdeg[i]   = 1.0f / (float)max(g_deg[i], 1);
    }
}

__global__ void fill_kernel(const void* __restrict__ ei, int E, int n) {
    int e = blockIdx.x * blockDim.x + threadIdx.x;
    if (e < E) {
        int src = load_idx(ei, e);
        int dst = load_idx(ei, (long long)E + e);
        if ((unsigned)dst < (unsigned)n && (unsigned)src < (unsigned)n) {
            int slot = atomicAdd(&g_cursor[dst], 1);
            if (slot < EMAX) g_csr[slot] = src;
        }
    }
}

// ---------------- gather-mean: one warp per node, conflict-free, no atomics ----------------

__device__ __forceinline__ void gather_impl(const float* __restrict__ feat,
                                            float* __restrict__ outp, int n) {
    int w    = (blockIdx.x * blockDim.x + threadIdx.x) >> 5;
    int lane = threadIdx.x & 31;
    if (w >= n) return;
    int s = g_rowstart[w];
    int e = g_rowstart[w + 1];
    const float4* f4 = (const float4*)feat;
    float4 a0 = make_float4(0.f, 0.f, 0.f, 0.f);
    float4 a1 = make_float4(0.f, 0.f, 0.f, 0.f);
    int i = s;
    for (; i + 32 <= e; i += 32) {
        int sv = g_csr[i + lane];
        #pragma unroll
        for (int j = 0; j < 32; j += 2) {
            int s0 = __shfl_sync(0xffffffffu, sv, j);
            int s1 = __shfl_sync(0xffffffffu, sv, j + 1);
            float4 v0 = f4[(size_t)s0 * 32 + lane];
            float4 v1 = f4[(size_t)s1 * 32 + lane];
            a0.x += v0.x; a0.y += v0.y; a0.z += v0.z; a0.w += v0.w;
            a1.x += v1.x; a1.y += v1.y; a1.z += v1.z; a1.w += v1.w;
        }
    }
    int rem = e - i;
    if (rem > 0) {
        int sv = (lane < rem) ? g_csr[i + lane] : 0;
        int j = 0;
        for (; j + 1 < rem; j += 2) {
            int s0 = __shfl_sync(0xffffffffu, sv, j);
            int s1 = __shfl_sync(0xffffffffu, sv, j + 1);
            float4 v0 = f4[(size_t)s0 * 32 + lane];
            float4 v1 = f4[(size_t)s1 * 32 + lane];
            a0.x += v0.x; a0.y += v0.y; a0.z += v0.z; a0.w += v0.w;
            a1.x += v1.x; a1.y += v1.y; a1.z += v1.z; a1.w += v1.w;
        }
        if (j < rem) {
            int s0 = __shfl_sync(0xffffffffu, sv, j);
            float4 v0 = f4[(size_t)s0 * 32 + lane];
            a0.x += v0.x; a0.y += v0.y; a0.z += v0.z; a0.w += v0.w;
        }
    }
    float id = g_invdeg[w];
    float4 r;
    r.x = (a0.x + a1.x) * id;
    r.y = (a0.y + a1.y) * id;
    r.z = (a0.z + a1.z) * id;
    r.w = (a0.w + a1.w) * id;
    ((float4*)outp)[(size_t)w * 32 + lane] = r;
}

__global__ __launch_bounds__(256) void gather1_kernel(const float* __restrict__ x, int n) {
    gather_impl(x, g_h1, n);
}
__global__ __launch_bounds__(256) void gather2_kernel(int n) {
    gather_impl(g_h2, g_h3, n);
}

// ---------------- GEMM1: h2 = relu(h1 @ W1 + b1) * mask ----------------
// BM=64, BN=128, BK=32. 256 threads, 4x8 register tile each. 24.7 KB static smem.

__global__ __launch_bounds__(256) void gemm1_kernel(const float* __restrict__ W1,
                                                    const float* __restrict__ b1,
                                                    const float* __restrict__ mask,
                                                    int n) {
    __shared__ __align__(16) float As[64 * 32];
    __shared__ __align__(16) float Ws[32 * 128];
    __shared__ __align__(16) float bs[128];
    int tid = threadIdx.x;

    if (tid < 32)
        ((float4*)bs)[tid] = ((const float4*)b1)[tid];

    int row0 = blockIdx.x * 64;
    int ty = tid >> 4, tx = tid & 15;
    float acc[4][8];
    #pragma unroll
    for (int i = 0; i < 4; i++)
        #pragma unroll
        for (int j = 0; j < 8; j++) acc[i][j] = 0.f;

    for (int kc = 0; kc < 4; kc++) {        // K chunks of 32
        #pragma unroll
        for (int t = 0; t < 2; t++) {
            int idx = tid + t * 256;        // 0..511
            int r = idx >> 3, c4 = idx & 7;
            int gr = row0 + r;
            float4 v = (gr < n) ? ((const float4*)g_h1)[(size_t)gr * 32 + kc * 8 + c4]
                                : make_float4(0.f, 0.f, 0.f, 0.f);
            *(float4*)&As[r * 32 + c4 * 4] = v;
        }
        #pragma unroll
        for (int t = 0; t < 4; t++) {
            int idx = tid + t * 256;        // 0..1023
            int r = idx >> 5, c4 = idx & 31;
            ((float4*)Ws)[idx] = ((const float4*)W1)[(size_t)(kc * 32 + r) * 32 + c4];
        }
        __syncthreads();

        #pragma unroll 8
        for (int kk = 0; kk < 32; kk++) {
            float4 w0 = *(float4*)&Ws[kk * 128 + tx * 4];
            float4 w1 = *(float4*)&Ws[kk * 128 + 64 + tx * 4];
            #pragma unroll
            for (int i = 0; i < 4; i++) {
                float a = As[(ty * 4 + i) * 32 + kk];
                acc[i][0] = fmaf(a, w0.x, acc[i][0]);
                acc[i][1] = fmaf(a, w0.y, acc[i][1]);
                acc[i][2] = fmaf(a, w0.z, acc[i][2]);
                acc[i][3] = fmaf(a, w0.w, acc[i][3]);
                acc[i][4] = fmaf(a, w1.x, acc[i][4]);
                acc[i][5] = fmaf(a, w1.y, acc[i][5]);
                acc[i][6] = fmaf(a, w1.z, acc[i][6]);
                acc[i][7] = fmaf(a, w1.w, acc[i][7]);
            }
        }
        __syncthreads();
    }

    float4 bv0 = *(float4*)&bs[tx * 4];
    float4 bv1 = *(float4*)&bs[64 + tx * 4];
    #pragma unroll
    for (int i = 0; i < 4; i++) {
        int gr = row0 + ty * 4 + i;
        if (gr < n) {
            float4 m0 = ((const float4*)mask)[(size_t)gr * 32 + tx];
            float4 m1 = ((const float4*)mask)[(size_t)gr * 32 + 16 + tx];
            float4 o0, o1;
            o0.x = fmaxf(acc[i][0] + bv0.x, 0.f) * m0.x;
            o0.y = fmaxf(acc[i][1] + bv0.y, 0.f) * m0.y;
            o0.z = fmaxf(acc[i][2] + bv0.z, 0.f) * m0.z;
            o0.w = fmaxf(acc[i][3] + bv0.w, 0.f) * m0.w;
            o1.x = fmaxf(acc[i][4] + bv1.x, 0.f) * m1.x;
            o1.y = fmaxf(acc[i][5] + bv1.y, 0.f) * m1.y;
            o1.z = fmaxf(acc[i][6] + bv1.z, 0.f) * m1.z;
            o1.w = fmaxf(acc[i][7] + bv1.w, 0.f) * m1.w;
            ((float4*)g_h2)[(size_t)gr * 32 + tx]      = o0;
            ((float4*)g_h2)[(size_t)gr * 32 + 16 + tx] = o1;
        }
    }
}

// ---------------- GEMM2: out = h3 @ W2 + b2  (C=16) ----------------

__global__ __launch_bounds__(128) void gemm2_kernel(const float* __restrict__ W2,
                                                    const float* __restrict__ b2,
                                                    float* __restrict__ out, int n) {
    __shared__ __align__(16) float As[32 * 132];
    __shared__ __align__(16) float W2s[128 * 16];
    __shared__ __align__(16) float b2s[16];
    int tid = threadIdx.x;

    for (int i = tid; i < 512; i += 128)
        ((float4*)W2s)[i] = ((const float4*)W2)[i];
    if (tid < 4)
        ((float4*)b2s)[tid] = ((const float4*)b2)[tid];

    int row0 = blockIdx.x * 32;
    for (int i = tid; i < 1024; i += 128) {
        int r = i >> 5, c4 = i & 31;
        int gr = row0 + r;
        float4 v = (gr < n) ? ((const float4*)g_h3)[(size_t)gr * 32 + c4]
                            : make_float4(0.f, 0.f, 0.f, 0.f);
        *(float4*)&As[r * 132 + c4 * 4] = v;
    }
    __syncthreads();

    int row = tid >> 2, cg = tid & 3;
    float4 acc = make_float4(0.f, 0.f, 0.f, 0.f);
    #pragma unroll 8
    for (int k = 0; k < 128; k++) {
        float a = As[row * 132 + k];
        float4 w = *(float4*)&W2s[k * 16 + cg * 4];
        acc.x = fmaf(a, w.x, acc.x);
        acc.y = fmaf(a, w.y, acc.y);
        acc.z = fmaf(a, w.z, acc.z);
        acc.w = fmaf(a, w.w, acc.w);
    }
    int gr = row0 + row;
    if (gr < n) {
        float4 b = *(float4*)&b2s[cg * 4];
        float4 o;
        o.x = acc.x + b.x; o.y = acc.y + b.y; o.z = acc.z + b.z; o.w = acc.w + b.w;
        ((float4*)out)[(size_t)gr * 4 + cg] = o;
    }
}

// ---------------- launch ----------------

extern "C" void kernel_launch(void* const* d_in, const int* in_sizes, int n_in,
                              void* d_out, int out_size) {
    const float* x    = (const float*)d_in[0];
    const void*  ei   = d_in[1];                 // int32 or int64, detected on device
    const float* W1   = (const float*)d_in[2];
    const float* b1   = (const float*)d_in[3];
    const float* W2   = (const float*)d_in[4];
    const float* b2   = (const float*)d_in[5];
    const float* mask = (const float*)d_in[6];
    float*       out  = (float*)d_out;

    int n = in_sizes[0] / 128;   // N nodes
    int E = in_sizes[1] / 2;     // edges (element count is 2E for either dtype)
    int nb = (n + SCAN_B - 1) / SCAN_B;

    // dtype detection + CSR build
    detect_kernel<<<1, 256>>>(ei, n);
    zero_deg_kernel<<<(n + 255) / 256, 256>>>(n);
    count_kernel<<<(E + 255) / 256, 256>>>(ei, E, n);
    scan_phase1<<<nb, SCAN_B>>>(n);
    scan_phase2<<<1, NBMAX>>>(nb, n);
    scan_phase3<<<nb, SCAN_B>>>(n);
    fill_kernel<<<(E + 255) / 256, 256>>>(ei, E, n);

    // layer 1
    gather1_kernel<<<(n * 32 + 255) / 256, 256>>>(x, n);
    gemm1_kernel<<<(n + 63) / 64, 256>>>(W1, b1, mask, n);

    // layer 2
    gather2_kernel<<<(n * 32 + 255) / 256, 256>>>(n);
    gemm2_kernel<<<(n + 31) / 32, 128>>>(W2, b2, out, n);
}